// round 1
// baseline (speedup 1.0000x reference)
#include <cuda_runtime.h>

// Problem shapes (fixed by reference setup_inputs)
#define N_ 128
#define D_ 2048
#define C_ 256
#define K_ 8192

// Scratch (no allocations allowed -> __device__ globals)
__device__ float g_penult[N_ * C_];
__device__ float g_invn[K_];

__device__ __forceinline__ float ex2f_(float x) {
    float y; asm("ex2.approx.f32 %0, %1;" : "=f"(y) : "f"(x)); return y;
}
__device__ __forceinline__ float lg2f_(float x) {
    float y; asm("lg2.approx.f32 %0, %1;" : "=f"(y) : "f"(x)); return y;
}

#define LOG2E 1.4426950408889634f
#define LN2   0.6931471805599453f
#define INV_T (1.0f / 0.07f)

// ---------------------------------------------------------------------------
// A) column inverse-norms of queue_logit [C, K] (normalize over axis 0)
//    grid: K/256 blocks x 256 threads; thread = one k column
// ---------------------------------------------------------------------------
__global__ void colnorm_kernel(const float* __restrict__ q) {
    int k = blockIdx.x * 256 + threadIdx.x;
    float ss = 0.0f;
#pragma unroll 8
    for (int c = 0; c < C_; c++) {
        float v = q[c * K_ + k];
        ss = fmaf(v, v, ss);
    }
    g_invn[k] = 1.0f / fmaxf(sqrtf(ss), 1e-12f);
}

// ---------------------------------------------------------------------------
// B) penult = img @ W_f + b_f   [N,D]x[D,C] -> [N,C]
//    4 rows of img per block staged in smem; thread = one output column c.
// ---------------------------------------------------------------------------
__global__ void gemm1_kernel(const float* __restrict__ img,
                             const float* __restrict__ Wf,
                             const float* __restrict__ bf) {
    __shared__ float si[4 * D_];   // 32 KB
    int n0 = blockIdx.x * 4;
    for (int i = threadIdx.x; i < 4 * D_; i += 256)
        si[i] = img[n0 * D_ + i];
    __syncthreads();

    int c = threadIdx.x;
    float b = bf[c];
    float a0 = b, a1 = b, a2 = b, a3 = b;
#pragma unroll 8
    for (int d = 0; d < D_; d++) {
        float w = Wf[d * C_ + c];
        a0 = fmaf(si[0 * D_ + d], w, a0);
        a1 = fmaf(si[1 * D_ + d], w, a1);
        a2 = fmaf(si[2 * D_ + d], w, a2);
        a3 = fmaf(si[3 * D_ + d], w, a3);
    }
    g_penult[(n0 + 0) * C_ + c] = a0;
    g_penult[(n0 + 1) * C_ + c] = a1;
    g_penult[(n0 + 2) * C_ + c] = a2;
    g_penult[(n0 + 3) * C_ + c] = a3;
}

// ---------------------------------------------------------------------------
// C) f_logit = penult @ W_c + b_c ; row L2-normalize ; l_pos = lse(dist*prob)
//    One block per row n (128 blocks x 256 threads). Writes f_logit and
//    logits[n][0] = l_pos / T.
// ---------------------------------------------------------------------------
__global__ void head_kernel(const float* __restrict__ Wc,
                            const float* __restrict__ bc,
                            const float* __restrict__ dist,
                            float* __restrict__ out) {
    __shared__ float sp[C_];
    __shared__ float sred[8];
    int n = blockIdx.x;
    int c = threadIdx.x;

    sp[c] = g_penult[n * C_ + c];
    __syncthreads();

    float acc = bc[c];
#pragma unroll 8
    for (int d = 0; d < C_; d++)
        acc = fmaf(sp[d], Wc[d * C_ + c], acc);

    // f_logit output region: after logits (N*(K+1)) and labels (N)
    out[N_ * (K_ + 1) + N_ + n * C_ + c] = acc;

    // block reduce sum of squares
    float v = acc * acc;
#pragma unroll
    for (int o = 16; o; o >>= 1) v += __shfl_xor_sync(0xffffffffu, v, o);
    if ((c & 31) == 0) sred[c >> 5] = v;
    __syncthreads();
    float ss = sred[0] + sred[1] + sred[2] + sred[3] +
               sred[4] + sred[5] + sred[6] + sred[7];
    __syncthreads();

    float inv = 1.0f / fmaxf(sqrtf(ss), 1e-12f);
    float t = dist[n * C_ + c] * acc * inv;   // |t| <= 1, safe direct lse
    float e = ex2f_(t * LOG2E);

#pragma unroll
    for (int o = 16; o; o >>= 1) e += __shfl_xor_sync(0xffffffffu, e, o);
    if ((c & 31) == 0) sred[c >> 5] = e;
    __syncthreads();
    if (c == 0) {
        float s = sred[0] + sred[1] + sred[2] + sred[3] +
                  sred[4] + sred[5] + sred[6] + sred[7];
        out[n * (K_ + 1)] = lg2f_(s) * (LN2 * INV_T);
    }
}

// ---------------------------------------------------------------------------
// labels = zeros[N] (int32 zeros == float 0.0f bits)
// ---------------------------------------------------------------------------
__global__ void labels_kernel(float* __restrict__ out) {
    out[N_ * (K_ + 1) + threadIdx.x] = 0.0f;
}

// ---------------------------------------------------------------------------
// D) l_neg[n,k] = log(sum_c exp(dist[n,c] * q[c,k] * invn[k])) / T
//    grid: (K/1024, N) blocks x 256 threads; each thread owns 4 k's.
//    |s| <= ~1.45 in log2 domain -> no max-subtraction needed.
// ---------------------------------------------------------------------------
__global__ void lneg_kernel(const float* __restrict__ dist,
                            const float* __restrict__ q,
                            float* __restrict__ out) {
    __shared__ float sd[C_];
    int n = blockIdx.y;
    sd[threadIdx.x] = dist[n * C_ + threadIdx.x] * LOG2E;
    __syncthreads();

    int k0 = (blockIdx.x * 256 + threadIdx.x) * 4;
    float4 iv = *reinterpret_cast<const float4*>(g_invn + k0);
    float a0 = 0.f, a1 = 0.f, a2 = 0.f, a3 = 0.f;
#pragma unroll 8
    for (int c = 0; c < C_; c++) {
        float d = sd[c];
        float4 qv = *reinterpret_cast<const float4*>(q + c * K_ + k0);
        a0 += ex2f_(d * qv.x * iv.x);
        a1 += ex2f_(d * qv.y * iv.y);
        a2 += ex2f_(d * qv.z * iv.z);
        a3 += ex2f_(d * qv.w * iv.w);
    }
    const float sc = LN2 * INV_T;
    int base = n * (K_ + 1) + 1 + k0;
    out[base + 0] = lg2f_(a0) * sc;
    out[base + 1] = lg2f_(a1) * sc;
    out[base + 2] = lg2f_(a2) * sc;
    out[base + 3] = lg2f_(a3) * sc;
}

extern "C" void kernel_launch(void* const* d_in, const int* in_sizes, int n_in,
                              void* d_out, int out_size) {
    const float* img  = (const float*)d_in[0];
    const float* Wf   = (const float*)d_in[1];
    const float* bf   = (const float*)d_in[2];
    const float* Wc   = (const float*)d_in[3];
    const float* bc   = (const float*)d_in[4];
    const float* dist = (const float*)d_in[5];
    const float* q    = (const float*)d_in[6];
    float* out = (float*)d_out;

    colnorm_kernel<<<K_ / 256, 256>>>(q);
    gemm1_kernel<<<N_ / 4, 256>>>(img, Wf, bf);
    head_kernel<<<N_, 256>>>(Wc, bc, dist, out);
    labels_kernel<<<1, N_>>>(out);
    lneg_kernel<<<dim3(K_ / 1024, N_), 256>>>(dist, q, out);
}

// round 2
// speedup vs baseline: 3.6896x; 3.6896x over previous
#include <cuda_runtime.h>
#include <cuda_bf16.h>
#include <cstdint>

#define N_ 128
#define D_ 2048
#define C_ 256
#define K_ 8192
#define NJ 4          // Taylor terms j=1..4 (j=0 handled as +256 constant)

#define LOG2E 1.4426950408889634f
#define LN2   0.6931471805599453f
#define INV_T (1.0f / 0.07f)

// Scratch (__device__ globals; no allocations allowed)
__device__ float g_penult[N_ * C_];
__device__ __nv_bfloat16 g_A[NJ * N_ * C_];   // A_j[n][c] = dist^j / j!  (bf16)

__device__ __forceinline__ float ex2f_(float x) {
    float y; asm("ex2.approx.f32 %0, %1;" : "=f"(y) : "f"(x)); return y;
}
__device__ __forceinline__ float lg2f_(float x) {
    float y; asm("lg2.approx.f32 %0, %1;" : "=f"(y) : "f"(x)); return y;
}
__device__ __forceinline__ uint32_t su32(const void* p) {
    return (uint32_t)__cvta_generic_to_shared(p);
}

// ---------------------------------------------------------------------------
// prep: build A powers (bf16), init penult with bias, zero labels
// grid 128 (one per n), block 256 (one per c)
// ---------------------------------------------------------------------------
__global__ void prep_kernel(const float* __restrict__ dist,
                            const float* __restrict__ bf,
                            float* __restrict__ out) {
    int n = blockIdx.x, c = threadIdx.x;
    float d = dist[n * C_ + c];
    float p = d;
    g_A[(0 * N_ + n) * C_ + c] = __float2bfloat16(p);
    p *= d;
    g_A[(1 * N_ + n) * C_ + c] = __float2bfloat16(p * 0.5f);
    p *= d;
    g_A[(2 * N_ + n) * C_ + c] = __float2bfloat16(p * (1.0f / 6.0f));
    p *= d;
    g_A[(3 * N_ + n) * C_ + c] = __float2bfloat16(p * (1.0f / 24.0f));
    g_penult[n * C_ + c] = bf[c];
    if (c == 0) out[N_ * (K_ + 1) + n] = 0.0f;   // labels
}

// ---------------------------------------------------------------------------
// gemm1: penult += img @ W_f  (fp32, split-K with atomics)
// grid (4 col-tiles of 64, 32 k-splits of 64), block 256
// ---------------------------------------------------------------------------
__global__ void gemm1_kernel(const float* __restrict__ img,
                             const float* __restrict__ Wf) {
    __shared__ float s_img[128][64];   // 32 KB
    int tid = threadIdx.x;
    int c = blockIdx.x * 64 + (tid & 63);
    int rblk = tid >> 6;               // 0..3 -> rows rblk*32..+31
    int d0 = blockIdx.y * 64;

    for (int i = tid; i < 128 * 64; i += 256) {
        int r = i >> 6, dd = i & 63;
        s_img[r][dd] = img[r * D_ + d0 + dd];
    }
    __syncthreads();

    float acc[32];
#pragma unroll
    for (int r = 0; r < 32; r++) acc[r] = 0.0f;

    for (int ds = 0; ds < 64; ds += 4) {
        float w0 = Wf[(d0 + ds + 0) * C_ + c];
        float w1 = Wf[(d0 + ds + 1) * C_ + c];
        float w2 = Wf[(d0 + ds + 2) * C_ + c];
        float w3 = Wf[(d0 + ds + 3) * C_ + c];
#pragma unroll
        for (int r = 0; r < 32; r++) {
            float4 v = *reinterpret_cast<const float4*>(&s_img[rblk * 32 + r][ds]);
            acc[r] = fmaf(v.x, w0, acc[r]);
            acc[r] = fmaf(v.y, w1, acc[r]);
            acc[r] = fmaf(v.z, w2, acc[r]);
            acc[r] = fmaf(v.w, w3, acc[r]);
        }
    }
#pragma unroll
    for (int r = 0; r < 32; r++)
        atomicAdd(&g_penult[(rblk * 32 + r) * C_ + c], acc[r]);
}

// ---------------------------------------------------------------------------
// head: f_logit = penult @ W_c + b_c ; row L2-norm ; l_pos (fp32 precision)
// ---------------------------------------------------------------------------
__global__ void head_kernel(const float* __restrict__ Wc,
                            const float* __restrict__ bc,
                            const float* __restrict__ dist,
                            float* __restrict__ out) {
    __shared__ float sp[C_];
    __shared__ float sred[8];
    int n = blockIdx.x;
    int c = threadIdx.x;

    sp[c] = g_penult[n * C_ + c];
    __syncthreads();

    float acc = bc[c];
#pragma unroll 8
    for (int d = 0; d < C_; d++)
        acc = fmaf(sp[d], Wc[d * C_ + c], acc);

    out[N_ * (K_ + 1) + N_ + n * C_ + c] = acc;   // f_logit

    float v = acc * acc;
#pragma unroll
    for (int o = 16; o; o >>= 1) v += __shfl_xor_sync(0xffffffffu, v, o);
    if ((c & 31) == 0) sred[c >> 5] = v;
    __syncthreads();
    float ss = sred[0] + sred[1] + sred[2] + sred[3] +
               sred[4] + sred[5] + sred[6] + sred[7];
    __syncthreads();

    float inv = 1.0f / fmaxf(sqrtf(ss), 1e-12f);
    float t = dist[n * C_ + c] * acc * inv;
    float e = ex2f_(t * LOG2E);
#pragma unroll
    for (int o = 16; o; o >>= 1) e += __shfl_xor_sync(0xffffffffu, e, o);
    if ((c & 31) == 0) sred[c >> 5] = e;
    __syncthreads();
    if (c == 0) {
        float s = sred[0] + sred[1] + sred[2] + sred[3] +
                  sred[4] + sred[5] + sred[6] + sred[7];
        out[n * (K_ + 1)] = lg2f_(s) * (LN2 * INV_T);
    }
}

// ---------------------------------------------------------------------------
// lneg via Taylor-GEMM on tensor cores (mma.sync bf16):
//   S[n,k] = sum_{j=1..4} A_j[n,:] . B_j[:,k],  B_j = (q*invn)^j
//   out = lg2(256 + S) * ln2 / T
// grid 128 (k-tiles of 64), block 256 (8 warps: 4 M x 2 N), dyn smem ~151KB
// ---------------------------------------------------------------------------
#define BROW 264     // B smem row stride (c-dim) in bf16, padded
#define AROW 72      // A smem row stride in bf16, padded
#define SM_B   0
#define SM_A   (NJ * 64 * BROW * 2)                 // 135168
#define SM_SS  (SM_A + 128 * AROW * 2)              // +18432
#define SM_INV (SM_SS + 4 * 64 * 4)                 // +1024
#define SM_TOT (SM_INV + 64 * 4)                    // +256 = 154880

__global__ void lneg_kernel(const float* __restrict__ q,
                            float* __restrict__ out) {
    extern __shared__ char smem[];
    __nv_bfloat16* Bs = (__nv_bfloat16*)(smem + SM_B);
    __nv_bfloat16* As = (__nv_bfloat16*)(smem + SM_A);
    float* sspart = (float*)(smem + SM_SS);
    float* invn   = (float*)(smem + SM_INV);

    int tid = threadIdx.x;
    int k0 = blockIdx.x * 64;
    int kx = tid & 63, cg = tid >> 6;

    // ---- column norms of this 64-column slab ----
    float ss = 0.0f;
    for (int c = cg; c < C_; c += 4) {
        float v = q[c * K_ + k0 + kx];
        ss = fmaf(v, v, ss);
    }
    sspart[cg * 64 + kx] = ss;
    __syncthreads();
    if (tid < 64) {
        float s = sspart[tid] + sspart[64 + tid] + sspart[128 + tid] + sspart[192 + tid];
        invn[tid] = 1.0f / fmaxf(sqrtf(s), 1e-12f);
    }
    __syncthreads();

    // ---- build B_j = b^j (bf16), layout [j][kcol][c] (B^T row-major) ----
    float iv = invn[kx];
    for (int c = cg; c < C_; c += 4) {
        float b = q[c * K_ + k0 + kx] * iv;
        float p = b;
        Bs[0 * 64 * BROW + kx * BROW + c] = __float2bfloat16(p);
        p *= b;
        Bs[1 * 64 * BROW + kx * BROW + c] = __float2bfloat16(p);
        p *= b;
        Bs[2 * 64 * BROW + kx * BROW + c] = __float2bfloat16(p);
        p *= b;
        Bs[3 * 64 * BROW + kx * BROW + c] = __float2bfloat16(p);
    }
    // (visibility of Bs guaranteed by the __syncthreads at top of chunk loop)

    int warp = tid >> 5, lane = tid & 31;
    int mrow = (warp >> 1) * 32;    // 4 warps along M
    int ncol = (warp & 1) * 32;     // 2 warps along N

    float acc[2][4][4];
#pragma unroll
    for (int mt = 0; mt < 2; mt++)
#pragma unroll
        for (int nt = 0; nt < 4; nt++)
#pragma unroll
            for (int i = 0; i < 4; i++) acc[mt][nt][i] = 0.0f;

    for (int j = 0; j < NJ; ++j) {
        const __nv_bfloat16* Asrc = g_A + (j * N_) * C_;
        for (int cc = 0; cc < 4; ++cc) {
            __syncthreads();
            // stage A chunk [128 x 64] into padded smem
#pragma unroll
            for (int t = 0; t < 4; ++t) {
                int lin = t * 256 + tid;
                int m = lin >> 3;
                int c8 = (lin & 7) << 3;
                *reinterpret_cast<uint4*>(As + m * AROW + c8) =
                    *reinterpret_cast<const uint4*>(Asrc + m * C_ + cc * 64 + c8);
            }
            __syncthreads();

            uint32_t Bj = su32(Bs) + (uint32_t)(j * 64 * BROW * 2);
            uint32_t Ab = su32(As);
#pragma unroll
            for (int ks = 0; ks < 4; ++ks) {
                uint32_t a[2][4];
#pragma unroll
                for (int mt = 0; mt < 2; ++mt) {
                    uint32_t addr = Ab + (uint32_t)(((mrow + mt * 16 + (lane & 15)) * AROW
                                                     + ks * 16 + (lane >> 4) * 8) * 2);
                    asm volatile("ldmatrix.sync.aligned.m8n8.x4.shared.b16 {%0,%1,%2,%3}, [%4];"
                                 : "=r"(a[mt][0]), "=r"(a[mt][1]), "=r"(a[mt][2]), "=r"(a[mt][3])
                                 : "r"(addr));
                }
                uint32_t bb[4][2];
#pragma unroll
                for (int nt = 0; nt < 4; ++nt) {
                    int nr = ncol + nt * 8 + (lane & 7);
                    uint32_t addr = Bj + (uint32_t)((nr * BROW + cc * 64 + ks * 16
                                                     + (((lane & 15) >> 3) * 8)) * 2);
                    asm volatile("ldmatrix.sync.aligned.m8n8.x2.shared.b16 {%0,%1}, [%2];"
                                 : "=r"(bb[nt][0]), "=r"(bb[nt][1])
                                 : "r"(addr));
                }
#pragma unroll
                for (int mt = 0; mt < 2; ++mt)
#pragma unroll
                    for (int nt = 0; nt < 4; ++nt)
                        asm volatile(
                            "mma.sync.aligned.m16n8k16.row.col.f32.bf16.bf16.f32 "
                            "{%0,%1,%2,%3}, {%4,%5,%6,%7}, {%8,%9}, {%0,%1,%2,%3};"
                            : "+f"(acc[mt][nt][0]), "+f"(acc[mt][nt][1]),
                              "+f"(acc[mt][nt][2]), "+f"(acc[mt][nt][3])
                            : "r"(a[mt][0]), "r"(a[mt][1]), "r"(a[mt][2]), "r"(a[mt][3]),
                              "r"(bb[nt][0]), "r"(bb[nt][1]));
            }
        }
    }

    // ---- epilogue: out = lg2(256 + S) * ln2 / T ----
    const float sc = LN2 * INV_T;
#pragma unroll
    for (int mt = 0; mt < 2; ++mt) {
#pragma unroll
        for (int nt = 0; nt < 4; ++nt) {
            int r = mrow + mt * 16 + (lane >> 2);
            int col = k0 + ncol + nt * 8 + (lane & 3) * 2;
            int base = r * (K_ + 1) + 1 + col;
            out[base]     = lg2f_(256.0f + acc[mt][nt][0]) * sc;
            out[base + 1] = lg2f_(256.0f + acc[mt][nt][1]) * sc;
            int base2 = (r + 8) * (K_ + 1) + 1 + col;
            out[base2]     = lg2f_(256.0f + acc[mt][nt][2]) * sc;
            out[base2 + 1] = lg2f_(256.0f + acc[mt][nt][3]) * sc;
        }
    }
}

extern "C" void kernel_launch(void* const* d_in, const int* in_sizes, int n_in,
                              void* d_out, int out_size) {
    const float* img  = (const float*)d_in[0];
    const float* Wf   = (const float*)d_in[1];
    const float* bf   = (const float*)d_in[2];
    const float* Wc   = (const float*)d_in[3];
    const float* bc   = (const float*)d_in[4];
    const float* dist = (const float*)d_in[5];
    const float* q    = (const float*)d_in[6];
    float* out = (float*)d_out;

    cudaFuncSetAttribute(lneg_kernel,
                         cudaFuncAttributeMaxDynamicSharedMemorySize, SM_TOT);

    prep_kernel<<<N_, C_>>>(dist, bf, out);
    gemm1_kernel<<<dim3(4, 32), 256>>>(img, Wf);
    head_kernel<<<N_, 256>>>(Wc, bc, dist, out);
    lneg_kernel<<<K_ / 64, 256, SM_TOT>>>(q, out);
}

// round 4
// speedup vs baseline: 4.7065x; 1.2756x over previous
#include <cuda_runtime.h>
#include <cuda_bf16.h>
#include <cstdint>

#define N_ 128
#define D_ 2048
#define C_ 256
#define K_ 8192
#define NJ 3          // Taylor terms j=1..3 (j=0 handled as +256 constant)

#define LOG2E 1.4426950408889634f
#define LN2   0.6931471805599453f
#define INV_T (1.0f / 0.07f)

__device__ float g_penult[N_ * C_];
__device__ __nv_bfloat16 g_A[NJ * N_ * C_];   // A_j[n][c] = dist^j / j!

__device__ __forceinline__ float ex2f_(float x) {
    float y; asm("ex2.approx.f32 %0, %1;" : "=f"(y) : "f"(x)); return y;
}
__device__ __forceinline__ float lg2f_(float x) {
    float y; asm("lg2.approx.f32 %0, %1;" : "=f"(y) : "f"(x)); return y;
}
__device__ __forceinline__ uint32_t su32(const void* p) {
    return (uint32_t)__cvta_generic_to_shared(p);
}
__device__ __forceinline__ uint32_t pack_bf2(float a, float b) {
    __nv_bfloat162 v = __floats2bfloat162_rn(a, b);
    return *reinterpret_cast<uint32_t*>(&v);
}

// ---------------------------------------------------------------------------
// prep: A powers (bf16), penult = bias, labels = 0
// ---------------------------------------------------------------------------
__global__ void prep_kernel(const float* __restrict__ dist,
                            const float* __restrict__ bf,
                            float* __restrict__ out) {
    int n = blockIdx.x, c = threadIdx.x;
    float d = dist[n * C_ + c];
    float p = d;
    g_A[(0 * N_ + n) * C_ + c] = __float2bfloat16(p);
    p *= d;
    g_A[(1 * N_ + n) * C_ + c] = __float2bfloat16(p * 0.5f);
    p *= d;
    g_A[(2 * N_ + n) * C_ + c] = __float2bfloat16(p * (1.0f / 6.0f));
    g_penult[n * C_ + c] = bf[c];
    if (c == 0) out[N_ * (K_ + 1) + n] = 0.0f;   // labels
}

// ---------------------------------------------------------------------------
// gemm1: penult += img @ W_f  (fp32 split-K, 256 CTAs)
// ---------------------------------------------------------------------------
__global__ void gemm1_kernel(const float* __restrict__ img,
                             const float* __restrict__ Wf) {
    __shared__ float s_img[128][32];   // 16 KB
    int tid = threadIdx.x;
    int c = blockIdx.x * 64 + (tid & 63);
    int rblk = tid >> 6;
    int d0 = blockIdx.y * 32;

    for (int i = tid; i < 128 * 32; i += 256) {
        int r = i >> 5, dd = i & 31;
        s_img[r][dd] = img[r * D_ + d0 + dd];
    }
    __syncthreads();

    float acc[32];
#pragma unroll
    for (int r = 0; r < 32; r++) acc[r] = 0.0f;

    for (int ds = 0; ds < 32; ds += 4) {
        float w0 = Wf[(d0 + ds + 0) * C_ + c];
        float w1 = Wf[(d0 + ds + 1) * C_ + c];
        float w2 = Wf[(d0 + ds + 2) * C_ + c];
        float w3 = Wf[(d0 + ds + 3) * C_ + c];
#pragma unroll
        for (int r = 0; r < 32; r++) {
            float4 v = *reinterpret_cast<const float4*>(&s_img[rblk * 32 + r][ds]);
            acc[r] = fmaf(v.x, w0, acc[r]);
            acc[r] = fmaf(v.y, w1, acc[r]);
            acc[r] = fmaf(v.z, w2, acc[r]);
            acc[r] = fmaf(v.w, w3, acc[r]);
        }
    }
#pragma unroll
    for (int r = 0; r < 32; r++)
        atomicAdd(&g_penult[(rblk * 32 + r) * C_ + c], acc[r]);
}

// ---------------------------------------------------------------------------
// head: f_logit + row norm + l_pos (fp32)
// ---------------------------------------------------------------------------
__global__ void head_kernel(const float* __restrict__ Wc,
                            const float* __restrict__ bc,
                            const float* __restrict__ dist,
                            float* __restrict__ out) {
    __shared__ float sp[C_];
    __shared__ float sred[8];
    int n = blockIdx.x;
    int c = threadIdx.x;

    sp[c] = g_penult[n * C_ + c];
    __syncthreads();

    float acc = bc[c];
#pragma unroll 8
    for (int d = 0; d < C_; d++)
        acc = fmaf(sp[d], Wc[d * C_ + c], acc);

    out[N_ * (K_ + 1) + N_ + n * C_ + c] = acc;

    float v = acc * acc;
#pragma unroll
    for (int o = 16; o; o >>= 1) v += __shfl_xor_sync(0xffffffffu, v, o);
    if ((c & 31) == 0) sred[c >> 5] = v;
    __syncthreads();
    float ss = sred[0] + sred[1] + sred[2] + sred[3] +
               sred[4] + sred[5] + sred[6] + sred[7];
    __syncthreads();

    float inv = 1.0f / fmaxf(sqrtf(ss), 1e-12f);
    float t = dist[n * C_ + c] * acc * inv;
    float e = ex2f_(t * LOG2E);
#pragma unroll
    for (int o = 16; o; o >>= 1) e += __shfl_xor_sync(0xffffffffu, e, o);
    if ((c & 31) == 0) sred[c >> 5] = e;
    __syncthreads();
    if (c == 0) {
        float s = sred[0] + sred[1] + sred[2] + sred[3] +
                  sred[4] + sred[5] + sred[6] + sred[7];
        out[n * (K_ + 1)] = lg2f_(s) * (LN2 * INV_T);
    }
}

// ---------------------------------------------------------------------------
// lneg: S = sum_j A_j @ B_j (bf16 mma), out = lg2(256+S)*ln2/T
// grid 128 (64-wide k tiles), block 512 (16 warps: 4M x 4N)
// smem: B_j all-resident; A staged once per j. Barrier-free kt loop.
// ---------------------------------------------------------------------------
#define BROW 264
#define AROW 72
#define SM_B   0
#define SM_A   (NJ * 64 * BROW * 2)                 // 101376
#define SM_SS  (SM_A + 128 * AROW * 2)              // 119808
#define SM_INV (SM_SS + 8 * 64 * 4)                 // 121856
#define SM_TOT (SM_INV + 64 * 4)                    // 122112

__global__ __launch_bounds__(512, 1)
void lneg_kernel(const float* __restrict__ q,
                 float* __restrict__ out) {
    extern __shared__ char smem[];
    __nv_bfloat16* Bs = (__nv_bfloat16*)(smem + SM_B);
    __nv_bfloat16* As = (__nv_bfloat16*)(smem + SM_A);
    float* sspart = (float*)(smem + SM_SS);
    float* invn   = (float*)(smem + SM_INV);

    int tid = threadIdx.x;
    int k0 = blockIdx.x * 64;
    int kx = tid & 63, cg = tid >> 6;   // cg 0..7

    // column sum-of-squares for this 64-column slab
    float ss = 0.0f;
    for (int c = cg; c < C_; c += 8) {
        float v = q[c * K_ + k0 + kx];
        ss = fmaf(v, v, ss);
    }
    sspart[cg * 64 + kx] = ss;
    __syncthreads();
    if (tid < 64) {
        float s = 0.0f;
#pragma unroll
        for (int g = 0; g < 8; g++) s += sspart[g * 64 + tid];
        invn[tid] = 1.0f / fmaxf(sqrtf(s), 1e-12f);
    }
    __syncthreads();

    // build B_j = b^j (bf16), layout [j][kcol][c]; pack pairs of c as u32 STS
    float iv = invn[kx];
#pragma unroll
    for (int i = 0; i < 16; ++i) {
        int c = cg * 2 + i * 16;
        float b0 = q[c * K_ + k0 + kx] * iv;
        float b1 = q[(c + 1) * K_ + k0 + kx] * iv;
        float p0 = b0, p1 = b1;
        uint32_t* dst0 = (uint32_t*)(Bs + 0 * 64 * BROW + kx * BROW + c);
        uint32_t* dst1 = (uint32_t*)(Bs + 1 * 64 * BROW + kx * BROW + c);
        uint32_t* dst2 = (uint32_t*)(Bs + 2 * 64 * BROW + kx * BROW + c);
        *dst0 = pack_bf2(p0, p1);
        p0 *= b0; p1 *= b1;
        *dst1 = pack_bf2(p0, p1);
        p0 *= b0; p1 *= b1;
        *dst2 = pack_bf2(p0, p1);
    }

    int warp = tid >> 5, lane = tid & 31;
    int mrow = (warp >> 2) * 32;     // 4 warps along M
    int ncol = (warp & 3) * 16;      // 4 warps along N

    float acc[2][2][4];
#pragma unroll
    for (int mt = 0; mt < 2; mt++)
#pragma unroll
        for (int nt = 0; nt < 2; nt++)
#pragma unroll
            for (int i = 0; i < 4; i++) acc[mt][nt][i] = 0.0f;

    uint32_t Ab = su32(As);
    for (int j = 0; j < NJ; ++j) {
        __syncthreads();   // B build done (j=0) / previous A consumption done
        // stage A_j [128 x 256] -> padded smem (8 uint4 per thread)
        const uint4* Asrc = (const uint4*)(g_A + (size_t)j * N_ * C_);
#pragma unroll
        for (int t = 0; t < 8; ++t) {
            int lin = t * 512 + tid;          // 0..4095
            int m = lin >> 5;
            int c8 = (lin & 31) * 8;
            *reinterpret_cast<uint4*>(As + m * AROW + c8) = Asrc[lin];
        }
        __syncthreads();

        uint32_t Bj = su32(Bs) + (uint32_t)(j * 64 * BROW * 2);
#pragma unroll
        for (int kt = 0; kt < 16; ++kt) {
            uint32_t a[2][4];
#pragma unroll
            for (int mt = 0; mt < 2; ++mt) {
                uint32_t addr = Ab + (uint32_t)(((mrow + mt * 16 + (lane & 15)) * AROW
                                                 + kt * 16 + (lane >> 4) * 8) * 2);
                asm volatile("ldmatrix.sync.aligned.m8n8.x4.shared.b16 {%0,%1,%2,%3}, [%4];"
                             : "=r"(a[mt][0]), "=r"(a[mt][1]), "=r"(a[mt][2]), "=r"(a[mt][3])
                             : "r"(addr));
            }
            uint32_t bb[2][2];
#pragma unroll
            for (int nt = 0; nt < 2; ++nt) {
                int nr = ncol + nt * 8 + (lane & 7);
                uint32_t addr = Bj + (uint32_t)((nr * BROW + kt * 16
                                                 + (((lane & 15) >> 3) * 8)) * 2);
                asm volatile("ldmatrix.sync.aligned.m8n8.x2.shared.b16 {%0,%1}, [%2];"
                             : "=r"(bb[nt][0]), "=r"(bb[nt][1])
                             : "r"(addr));
            }
#pragma unroll
            for (int mt = 0; mt < 2; ++mt)
#pragma unroll
                for (int nt = 0; nt < 2; ++nt)
                    asm volatile(
                        "mma.sync.aligned.m16n8k16.row.col.f32.bf16.bf16.f32 "
                        "{%0,%1,%2,%3}, {%4,%5,%6,%7}, {%8,%9}, {%0,%1,%2,%3};"
                        : "+f"(acc[mt][nt][0]), "+f"(acc[mt][nt][1]),
                          "+f"(acc[mt][nt][2]), "+f"(acc[mt][nt][3])
                        : "r"(a[mt][0]), "r"(a[mt][1]), "r"(a[mt][2]), "r"(a[mt][3]),
                          "r"(bb[nt][0]), "r"(bb[nt][1]));
        }
    }

    // epilogue: out = lg2(256 + S) * ln2 / T
    const float sc = LN2 * INV_T;
#pragma unroll
    for (int mt = 0; mt < 2; ++mt) {
#pragma unroll
        for (int nt = 0; nt < 2; ++nt) {
            int r = mrow + mt * 16 + (lane >> 2);
            int col = k0 + ncol + nt * 8 + (lane & 3) * 2;
            int base = r * (K_ + 1) + 1 + col;
            out[base]     = lg2f_(256.0f + acc[mt][nt][0]) * sc;
            out[base + 1] = lg2f_(256.0f + acc[mt][nt][1]) * sc;
            int base2 = (r + 8) * (K_ + 1) + 1 + col;
            out[base2]     = lg2f_(256.0f + acc[mt][nt][2]) * sc;
            out[base2 + 1] = lg2f_(256.0f + acc[mt][nt][3]) * sc;
        }
    }
}

extern "C" void kernel_launch(void* const* d_in, const int* in_sizes, int n_in,
                              void* d_out, int out_size) {
    const float* img  = (const float*)d_in[0];
    const float* Wf   = (const float*)d_in[1];
    const float* bf   = (const float*)d_in[2];
    const float* Wc   = (const float*)d_in[3];
    const float* bc   = (const float*)d_in[4];
    const float* dist = (const float*)d_in[5];
    const float* q    = (const float*)d_in[6];
    float* out = (float*)d_out;

    cudaFuncSetAttribute(lneg_kernel,
                         cudaFuncAttributeMaxDynamicSharedMemorySize, SM_TOT);

    prep_kernel<<<N_, C_>>>(dist, bf, out);
    gemm1_kernel<<<dim3(4, 64), 256>>>(img, Wf);
    head_kernel<<<N_, 256>>>(Wc, bc, dist, out);
    lneg_kernel<<<K_ / 64, 512, SM_TOT>>>(q, out);
}

// round 6
// speedup vs baseline: 5.1793x; 1.1005x over previous
#include <cuda_runtime.h>
#include <cuda_bf16.h>
#include <cstdint>

#define N_ 128
#define D_ 2048
#define C_ 256
#define K_ 8192
#define NJ 3          // Taylor terms j=1..3 (j=0 handled as +256 constant)

#define LOG2E 1.4426950408889634f
#define LN2   0.6931471805599453f
#define INV_T (1.0f / 0.07f)

__device__ float g_penult[N_ * C_];
__device__ __nv_bfloat16 g_A[NJ * N_ * C_];   // A_j[n][c] = dist^j / j!

__device__ __forceinline__ float ex2f_(float x) {
    float y; asm("ex2.approx.f32 %0, %1;" : "=f"(y) : "f"(x)); return y;
}
__device__ __forceinline__ float lg2f_(float x) {
    float y; asm("lg2.approx.f32 %0, %1;" : "=f"(y) : "f"(x)); return y;
}
__device__ __forceinline__ uint32_t su32(const void* p) {
    return (uint32_t)__cvta_generic_to_shared(p);
}
__device__ __forceinline__ uint32_t pack_bf2(float a, float b) {
    __nv_bfloat162 v = __floats2bfloat162_rn(a, b);
    return *reinterpret_cast<uint32_t*>(&v);
}

// ---------------------------------------------------------------------------
// prep: A powers (bf16), penult = bias, labels = 0
// ---------------------------------------------------------------------------
__global__ void prep_kernel(const float* __restrict__ dist,
                            const float* __restrict__ bf,
                            float* __restrict__ out) {
    int n = blockIdx.x, c = threadIdx.x;
    float d = dist[n * C_ + c];
    float p = d;
    g_A[(0 * N_ + n) * C_ + c] = __float2bfloat16(p);
    p *= d;
    g_A[(1 * N_ + n) * C_ + c] = __float2bfloat16(p * 0.5f);
    p *= d;
    g_A[(2 * N_ + n) * C_ + c] = __float2bfloat16(p * (1.0f / 6.0f));
    g_penult[n * C_ + c] = bf[c];
    if (c == 0) out[N_ * (K_ + 1) + n] = 0.0f;   // labels
}

// ---------------------------------------------------------------------------
// gemm1: penult += img @ W_f  (fp32 split-K, 256 CTAs)
// ---------------------------------------------------------------------------
__global__ void gemm1_kernel(const float* __restrict__ img,
                             const float* __restrict__ Wf) {
    __shared__ float s_img[128][32];   // 16 KB
    int tid = threadIdx.x;
    int c = blockIdx.x * 64 + (tid & 63);
    int rblk = tid >> 6;
    int d0 = blockIdx.y * 32;

    for (int i = tid; i < 128 * 32; i += 256) {
        int r = i >> 5, dd = i & 31;
        s_img[r][dd] = img[r * D_ + d0 + dd];
    }
    __syncthreads();

    float acc[32];
#pragma unroll
    for (int r = 0; r < 32; r++) acc[r] = 0.0f;

    for (int ds = 0; ds < 32; ds += 4) {
        float w0 = Wf[(d0 + ds + 0) * C_ + c];
        float w1 = Wf[(d0 + ds + 1) * C_ + c];
        float w2 = Wf[(d0 + ds + 2) * C_ + c];
        float w3 = Wf[(d0 + ds + 3) * C_ + c];
#pragma unroll
        for (int r = 0; r < 32; r++) {
            float4 v = *reinterpret_cast<const float4*>(&s_img[rblk * 32 + r][ds]);
            acc[r] = fmaf(v.x, w0, acc[r]);
            acc[r] = fmaf(v.y, w1, acc[r]);
            acc[r] = fmaf(v.z, w2, acc[r]);
            acc[r] = fmaf(v.w, w3, acc[r]);
        }
    }
#pragma unroll
    for (int r = 0; r < 32; r++)
        atomicAdd(&g_penult[(rblk * 32 + r) * C_ + c], acc[r]);
}

// ---------------------------------------------------------------------------
// head: f_logit + row norm + l_pos (fp32)
// ---------------------------------------------------------------------------
__global__ void head_kernel(const float* __restrict__ Wc,
                            const float* __restrict__ bc,
                            const float* __restrict__ dist,
                            float* __restrict__ out) {
    __shared__ float sp[C_];
    __shared__ float sred[8];
    int n = blockIdx.x;
    int c = threadIdx.x;

    sp[c] = g_penult[n * C_ + c];
    __syncthreads();

    float acc = bc[c];
#pragma unroll 8
    for (int d = 0; d < C_; d++)
        acc = fmaf(sp[d], Wc[d * C_ + c], acc);

    out[N_ * (K_ + 1) + N_ + n * C_ + c] = acc;

    float v = acc * acc;
#pragma unroll
    for (int o = 16; o; o >>= 1) v += __shfl_xor_sync(0xffffffffu, v, o);
    if ((c & 31) == 0) sred[c >> 5] = v;
    __syncthreads();
    float ss = sred[0] + sred[1] + sred[2] + sred[3] +
               sred[4] + sred[5] + sred[6] + sred[7];
    __syncthreads();

    float inv = 1.0f / fmaxf(sqrtf(ss), 1e-12f);
    float t = dist[n * C_ + c] * acc * inv;
    float e = ex2f_(t * LOG2E);
#pragma unroll
    for (int o = 16; o; o >>= 1) e += __shfl_xor_sync(0xffffffffu, e, o);
    if ((c & 31) == 0) sred[c >> 5] = e;
    __syncthreads();
    if (c == 0) {
        float s = sred[0] + sred[1] + sred[2] + sred[3] +
                  sred[4] + sred[5] + sred[6] + sred[7];
        out[n * (K_ + 1)] = lg2f_(s) * (LN2 * INV_T);
    }
}

// ---------------------------------------------------------------------------
// lneg: S = sum_j A_j @ B_j (bf16 mma.sync), out = lg2(256+S)*ln2/T
// grid 128 (64-wide k tiles), block 512 (16 warps: 4M x 4N)
// smem: B_j all-resident [j][kcol][c pad 264]; A_j full [128][264] staged per j.
// ---------------------------------------------------------------------------
#define BROW 264
#define AROW 264
#define SM_B   0
#define SM_A   (NJ * 64 * BROW * 2)                 // 101376
#define SM_SS  (SM_A + 128 * AROW * 2)              // 168960
#define SM_INV (SM_SS + 8 * 64 * 4)                 // 171008
#define SM_TOT (SM_INV + 64 * 4)                    // 171264

__global__ __launch_bounds__(512, 1)
void lneg_kernel(const float* __restrict__ q,
                 float* __restrict__ out) {
    extern __shared__ char smem[];
    __nv_bfloat16* Bs = (__nv_bfloat16*)(smem + SM_B);
    __nv_bfloat16* As = (__nv_bfloat16*)(smem + SM_A);
    float* sspart = (float*)(smem + SM_SS);
    float* invn   = (float*)(smem + SM_INV);

    int tid = threadIdx.x;
    int k0 = blockIdx.x * 64;
    int kx = tid & 63, cg = tid >> 6;   // cg 0..7

    // column sum-of-squares for this 64-column slab
    float ss = 0.0f;
    for (int c = cg; c < C_; c += 8) {
        float v = q[c * K_ + k0 + kx];
        ss = fmaf(v, v, ss);
    }
    sspart[cg * 64 + kx] = ss;
    __syncthreads();
    if (tid < 64) {
        float s = 0.0f;
#pragma unroll
        for (int g = 0; g < 8; g++) s += sspart[g * 64 + tid];
        invn[tid] = 1.0f / fmaxf(sqrtf(s), 1e-12f);
    }
    __syncthreads();

    // build B_j = b^j (bf16), layout [j][kcol][c]; pack pairs of c as u32 STS
    float iv = invn[kx];
#pragma unroll
    for (int i = 0; i < 16; ++i) {
        int c = cg * 2 + i * 16;
        float b0 = q[c * K_ + k0 + kx] * iv;
        float b1 = q[(c + 1) * K_ + k0 + kx] * iv;
        float p0 = b0, p1 = b1;
        uint32_t* dst0 = (uint32_t*)(Bs + 0 * 64 * BROW + kx * BROW + c);
        uint32_t* dst1 = (uint32_t*)(Bs + 1 * 64 * BROW + kx * BROW + c);
        uint32_t* dst2 = (uint32_t*)(Bs + 2 * 64 * BROW + kx * BROW + c);
        *dst0 = pack_bf2(p0, p1);
        p0 *= b0; p1 *= b1;
        *dst1 = pack_bf2(p0, p1);
        p0 *= b0; p1 *= b1;
        *dst2 = pack_bf2(p0, p1);
    }

    int warp = tid >> 5, lane = tid & 31;
    int mrow = (warp >> 2) * 32;     // 4 warps along M
    int ncol = (warp & 3) * 16;      // 4 warps along N

    float acc[2][2][4];
#pragma unroll
    for (int mt = 0; mt < 2; mt++)
#pragma unroll
        for (int nt = 0; nt < 2; nt++)
#pragma unroll
            for (int i = 0; i < 4; i++) acc[mt][nt][i] = 0.0f;

    uint32_t Ab = su32(As);
    for (int j = 0; j < NJ; ++j) {
        __syncthreads();   // B build done (j=0) / previous A consumption done
        // stage A_j [128 x 256] -> padded [128][264] smem (8 uint4 per thread)
        const uint4* Asrc = (const uint4*)(g_A + (size_t)j * N_ * C_);
#pragma unroll
        for (int t = 0; t < 8; ++t) {
            int lin = t * 512 + tid;          // 0..4095 uint4s
            int m = lin >> 5;                 // 0..127
            int c8 = (lin & 31) * 8;          // 0..248
            *reinterpret_cast<uint4*>(As + m * AROW + c8) = Asrc[lin];
        }
        __syncthreads();

        uint32_t Bj = su32(Bs) + (uint32_t)(j * 64 * BROW * 2);
#pragma unroll
        for (int kt = 0; kt < 16; ++kt) {
            uint32_t a[2][4];
#pragma unroll
            for (int mt = 0; mt < 2; ++mt) {
                uint32_t addr = Ab + (uint32_t)(((mrow + mt * 16 + (lane & 15)) * AROW
                                                 + kt * 16 + (lane >> 4) * 8) * 2);
                asm volatile("ldmatrix.sync.aligned.m8n8.x4.shared.b16 {%0,%1,%2,%3}, [%4];"
                             : "=r"(a[mt][0]), "=r"(a[mt][1]), "=r"(a[mt][2]), "=r"(a[mt][3])
                             : "r"(addr));
            }
            uint32_t bb[2][2];
#pragma unroll
            for (int nt = 0; nt < 2; ++nt) {
                int nr = ncol + nt * 8 + (lane & 7);
                uint32_t addr = Bj + (uint32_t)((nr * BROW + kt * 16
                                                 + (((lane & 15) >> 3) * 8)) * 2);
                asm volatile("ldmatrix.sync.aligned.m8n8.x2.shared.b16 {%0,%1}, [%2];"
                             : "=r"(bb[nt][0]), "=r"(bb[nt][1])
                             : "r"(addr));
            }
#pragma unroll
            for (int mt = 0; mt < 2; ++mt)
#pragma unroll
                for (int nt = 0; nt < 2; ++nt)
                    asm volatile(
                        "mma.sync.aligned.m16n8k16.row.col.f32.bf16.bf16.f32 "
                        "{%0,%1,%2,%3}, {%4,%5,%6,%7}, {%8,%9}, {%0,%1,%2,%3};"
                        : "+f"(acc[mt][nt][0]), "+f"(acc[mt][nt][1]),
                          "+f"(acc[mt][nt][2]), "+f"(acc[mt][nt][3])
                        : "r"(a[mt][0]), "r"(a[mt][1]), "r"(a[mt][2]), "r"(a[mt][3]),
                          "r"(bb[nt][0]), "r"(bb[nt][1]));
        }
    }

    // epilogue: out = lg2(256 + S) * ln2 / T
    const float sc = LN2 * INV_T;
#pragma unroll
    for (int mt = 0; mt < 2; ++mt) {
#pragma unroll
        for (int nt = 0; nt < 2; ++nt) {
            int r = mrow + mt * 16 + (lane >> 2);
            int col = k0 + ncol + nt * 8 + (lane & 3) * 2;
            int base = r * (K_ + 1) + 1 + col;
            out[base]     = lg2f_(256.0f + acc[mt][nt][0]) * sc;
            out[base + 1] = lg2f_(256.0f + acc[mt][nt][1]) * sc;
            int base2 = (r + 8) * (K_ + 1) + 1 + col;
            out[base2]     = lg2f_(256.0f + acc[mt][nt][2]) * sc;
            out[base2 + 1] = lg2f_(256.0f + acc[mt][nt][3]) * sc;
        }
    }
}

extern "C" void kernel_launch(void* const* d_in, const int* in_sizes, int n_in,
                              void* d_out, int out_size) {
    const float* img  = (const float*)d_in[0];
    const float* Wf   = (const float*)d_in[1];
    const float* bf   = (const float*)d_in[2];
    const float* Wc   = (const float*)d_in[3];
    const float* bc   = (const float*)d_in[4];
    const float* dist = (const float*)d_in[5];
    const float* q    = (const float*)d_in[6];
    float* out = (float*)d_out;

    // One-time host resource setup (no device memory; streams/events are
    // created outside any capture on the first (correctness) call).
    static cudaStream_t s1 = nullptr;
    static cudaEvent_t ev0 = nullptr, ev1 = nullptr;
    if (s1 == nullptr) {
        cudaStreamCreateWithFlags(&s1, cudaStreamNonBlocking);
        cudaEventCreateWithFlags(&ev0, cudaEventDisableTiming);
        cudaEventCreateWithFlags(&ev1, cudaEventDisableTiming);
        cudaFuncSetAttribute(lneg_kernel,
                             cudaFuncAttributeMaxDynamicSharedMemorySize, SM_TOT);
    }

    // prep -> fork: {lneg on main} || {gemm1 -> head on s1} -> join
    prep_kernel<<<N_, C_>>>(dist, bf, out);
    cudaEventRecord(ev0, 0);
    cudaStreamWaitEvent(s1, ev0, 0);
    gemm1_kernel<<<dim3(4, 64), 256, 0, s1>>>(img, Wf);
    head_kernel<<<N_, 256, 0, s1>>>(Wc, bc, dist, out);
    cudaEventRecord(ev1, s1);
    lneg_kernel<<<K_ / 64, 512, SM_TOT>>>(q, out);
    cudaStreamWaitEvent(0, ev1, 0);
}